// round 10
// baseline (speedup 1.0000x reference)
#include <cuda_runtime.h>

#define BATCH   64
#define N       128
#define LAYERS  128
#define PAIRS   64
#define STEEP   10.0f
#define INV_PI  0.318309886183790671538f
#define FULL    0xffffffffu
#define CHUNK   8

// alphas[batch][layer][pair] (2 MB) + per-batch progress flags
__device__ float g_alphas[BATCH * LAYERS * PAIRS];
__device__ int   g_flag[BATCH];

typedef unsigned long long u64;

static __device__ __forceinline__ u64 pk2(float lo, float hi) {
    u64 r; asm("mov.b64 %0, {%1, %2};" : "=l"(r) : "f"(lo), "f"(hi)); return r;
}
static __device__ __forceinline__ void upk2(u64 v, float& lo, float& hi) {
    asm("mov.b64 {%0, %1}, %2;" : "=f"(lo), "=f"(hi) : "l"(v));
}
static __device__ __forceinline__ u64 fma2_(u64 a, u64 b, u64 c) {
    u64 d; asm("fma.rn.f32x2 %0, %1, %2, %3;" : "=l"(d) : "l"(a), "l"(b), "l"(c)); return d;
}
static __device__ __forceinline__ u64 add2_(u64 a, u64 b) {
    u64 d; asm("add.rn.f32x2 %0, %1, %2;" : "=l"(d) : "l"(a), "l"(b)); return d;
}
static __device__ __forceinline__ u64 neg2_(u64 a) { return a ^ 0x8000000080000000ULL; }

static __device__ __forceinline__ u64 shfl_dn2(u64 v) {
    float a, b; upk2(v, a, b);
    a = __shfl_down_sync(FULL, a, 1);
    b = __shfl_down_sync(FULL, b, 1);
    return pk2(a, b);
}
static __device__ __forceinline__ u64 shfl_up2(u64 v) {
    float a, b; upk2(v, a, b);
    a = __shfl_up_sync(FULL, a, 1);
    b = __shfl_up_sync(FULL, b, 1);
    return pk2(a, b);
}

// soft compare-exchange alpha for pair (a, b)
static __device__ __forceinline__ float soft_alpha(float a, float b) {
    return atanf(STEEP * (b - a)) * INV_PI + 0.5f;
}

__global__ void reset_kernel() { g_flag[threadIdx.x] = 0; }

// ---------------------------------------------------------------------------
// Fused kernel.
//   CTAs 0..7      : producers. 8 warps each; warp w handles batch 8*bid+w.
//                    Serial 128-layer chain, halo ghosts (no shuffles on the
//                    critical path), publishes alphas every CHUNK layers.
//   CTAs 8..263    : consumers. 4 CTAs per batch, 8 warps, 4 rows per warp
//                    packed two-rows-per-register with f32x2 FMA.
// ---------------------------------------------------------------------------
__global__ __launch_bounds__(256) void fused_kernel(const float* __restrict__ in,
                                                    float* __restrict__ out) {
    const int tid  = threadIdx.x;
    const int warp = tid >> 5;
    const int lane = tid & 31;

    if (blockIdx.x < 8) {
        // ===================== PRODUCER =====================
        const int b = blockIdx.x * 8 + warp;
        const int l = lane;

        const float4 xi = ((const float4*)(in + b * N))[l];
        float x0 = xi.x, x1 = xi.y, x2 = xi.z, x3 = xi.w;

        float2* aout = (float2*)(g_alphas + (size_t)b * LAYERS * PAIRS);
        int*    flagp = &g_flag[b];

        for (int L = 0; L < LAYERS; L += 2) {
            // ghost refresh (reads PREVIOUS iteration values -> off the chain)
            float gr0 = __shfl_down_sync(FULL, x0, 1); // next lane x0
            float gr1 = __shfl_down_sync(FULL, x1, 1); // next lane x1
            float gl2 = __shfl_up_sync  (FULL, x2, 1); // prev lane x2
            float gl3 = __shfl_up_sync  (FULL, x3, 1); // prev lane x3

            // ---- even layer L ----
            float d0  = x0 - x1,  d1  = x2 - x3;
            float dgr = gr0 - gr1, dgl = gl2 - gl3;
            float al0 = soft_alpha(x0, x1);
            float al1 = soft_alpha(x2, x3);
            float agr = soft_alpha(gr0, gr1);
            float agl = soft_alpha(gl2, gl3);
            float n0 = fmaf(al0, d0, x1);
            float n1 = fmaf(-al0, d0, x0);
            float n2 = fmaf(al1, d1, x3);
            float n3 = fmaf(-al1, d1, x2);
            float gr0n = fmaf(agr, dgr, gr1);   // neighbor's new x0 (exact replica)
            float gl3n = fmaf(-agl, dgl, gl2);  // prev neighbor's new x3
            x0 = n0; x1 = n1; x2 = n2; x3 = n3;
            aout[L * 32 + l] = make_float2(al0, al1);

            // ---- odd layer L+1 (fully local) ----
            float dm = x1 - x2;
            float am = soft_alpha(x1, x2);
            float dc = x3 - gr0n;
            float ac = soft_alpha(x3, gr0n);            // pair (4l+3, 4l+4)
            float dl = gl3n - x0;
            float apre = soft_alpha(gl3n, x0);          // pair (4l-1, 4l)
            float nx1 = fmaf(am, dm, x2);
            float nx2 = fmaf(-am, dm, x1);
            x3 = (l < 31) ? fmaf(ac, dc, gr0n) : x3;    // new a of cross pair
            x0 = (l > 0)  ? fmaf(-apre, dl, gl3n) : x0; // new b of left pair
            x1 = nx1; x2 = nx2;
            aout[(L + 1) * 32 + l] = make_float2(am, ac);

            // publish completed layers every CHUNK
            if (((L + 2) & (CHUNK - 1)) == 0) {
                __syncwarp();
                __threadfence();
                if (l == 0)
                    asm volatile("st.release.gpu.b32 [%0], %1;"
                                 :: "l"(flagp), "r"(L + 2) : "memory");
            }
        }

        ((float4*)(out + b * N))[l] = make_float4(x0, x1, x2, x3);

    } else {
        // ===================== CONSUMER =====================
        const int cid = blockIdx.x - 8;
        const int b   = cid >> 2;          // 4 CTAs per batch
        const int grp = cid & 3;
        const int row0 = grp * 32 + warp * 4;

        // 4 rows per warp: 2 packed row-pairs, lane owns cols 4*lane..4*lane+3
        u64 P[2][4];
        #pragma unroll
        for (int pp = 0; pp < 2; ++pp)
            #pragma unroll
            for (int j = 0; j < 4; ++j) {
                int col = 4 * lane + j;
                P[pp][j] = pk2((row0 + 2 * pp)     == col ? 1.0f : 0.0f,
                               (row0 + 2 * pp + 1) == col ? 1.0f : 0.0f);
            }

        const float2* Af2 = (const float2*)(g_alphas + (size_t)b * LAYERS * PAIRS);
        int* flagp = &g_flag[b];

        for (int chunk = 0; chunk < LAYERS / CHUNK; ++chunk) {
            const int target = (chunk + 1) * CHUNK;
            int f;
            do {
                asm volatile("ld.acquire.gpu.b32 %0, [%1];"
                             : "=r"(f) : "l"(flagp) : "memory");
            } while (f < target);

            #pragma unroll
            for (int Li = 0; Li < CHUNK; Li += 2) {
                const int L = chunk * CHUNK + Li;

                // ---- even layer ----
                float2 aE = Af2[L * 32 + lane];
                u64 a0s = pk2(aE.x, aE.x);
                u64 a1s = pk2(aE.y, aE.y);
                #pragma unroll
                for (int pp = 0; pp < 2; ++pp) {
                    u64 d0 = add2_(P[pp][0], neg2_(P[pp][1]));
                    u64 c0 = fma2_(a0s, d0, P[pp][1]);
                    u64 c1 = fma2_(a0s, neg2_(d0), P[pp][0]);
                    P[pp][0] = c0; P[pp][1] = c1;
                    u64 d1 = add2_(P[pp][2], neg2_(P[pp][3]));
                    u64 c2 = fma2_(a1s, d1, P[pp][3]);
                    u64 c3 = fma2_(a1s, neg2_(d1), P[pp][2]);
                    P[pp][2] = c2; P[pp][3] = c3;
                }

                // ---- odd layer ----
                float2 aO = Af2[(L + 1) * 32 + lane];
                float ap  = __shfl_up_sync(FULL, aO.y, 1);
                float b1z = (lane == 31) ? 0.0f : (1.0f - aO.y);
                float bpz = (lane == 0)  ? 0.0f : (1.0f - ap);
                u64 ams = pk2(aO.x, aO.x);
                u64 b1s = pk2(b1z, b1z);
                u64 bps = pk2(bpz, bpz);
                #pragma unroll
                for (int pp = 0; pp < 2; ++pp) {
                    u64 nb = shfl_dn2(P[pp][0]);  // next lane's col 4l+4 values
                    u64 pa = shfl_up2(P[pp][3]);  // prev lane's col 4l-1 values
                    u64 d  = add2_(P[pp][1], neg2_(P[pp][2]));
                    u64 n1 = fma2_(ams, d, P[pp][2]);
                    u64 n2 = fma2_(ams, neg2_(d), P[pp][1]);
                    P[pp][3] = fma2_(b1s, add2_(nb, neg2_(P[pp][3])), P[pp][3]); // no-op lane31
                    P[pp][0] = fma2_(bps, add2_(pa, neg2_(P[pp][0])), P[pp][0]); // no-op lane0
                    P[pp][1] = n1; P[pp][2] = n2;
                }
            }
        }

        float* outb = out + BATCH * N + (size_t)b * N * N;
        #pragma unroll
        for (int pp = 0; pp < 2; ++pp) {
            float r0v[4], r1v[4];
            #pragma unroll
            for (int j = 0; j < 4; ++j) upk2(P[pp][j], r0v[j], r1v[j]);
            ((float4*)(outb + (row0 + 2 * pp) * N))[lane] =
                make_float4(r0v[0], r0v[1], r0v[2], r0v[3]);
            ((float4*)(outb + (row0 + 2 * pp + 1) * N))[lane] =
                make_float4(r1v[0], r1v[1], r1v[2], r1v[3]);
        }
    }
}

extern "C" void kernel_launch(void* const* d_in, const int* in_sizes, int n_in,
                              void* d_out, int out_size) {
    (void)in_sizes; (void)n_in; (void)out_size;
    const float* vec = (const float*)d_in[0];
    float* out = (float*)d_out;

    reset_kernel<<<1, BATCH>>>();
    // output layout: [x (64*128)] then [X (64*128*128)]
    fused_kernel<<<8 + BATCH * 4, 256>>>(vec, out);
}

// round 11
// speedup vs baseline: 2.6657x; 2.6657x over previous
#include <cuda_runtime.h>

#define BATCH   64
#define N       128
#define LAYERS  128
#define PAIRS   64
#define STEEP   10.0f
#define INV_PI  0.318309886183790671538f
#define FULL    0xffffffffu

// alphas[batch][layer_pair][pair] as float4 {al0,al1,am,ac}  (2 MB)
__device__ float4 g_alphas4[BATCH * (LAYERS / 2) * 32];

typedef unsigned long long u64;

static __device__ __forceinline__ u64 pk2(float lo, float hi) {
    u64 r; asm("mov.b64 %0, {%1, %2};" : "=l"(r) : "f"(lo), "f"(hi)); return r;
}
static __device__ __forceinline__ void upk2(u64 v, float& lo, float& hi) {
    asm("mov.b64 {%0, %1}, %2;" : "=f"(lo), "=f"(hi) : "l"(v));
}
static __device__ __forceinline__ u64 fma2_(u64 a, u64 b, u64 c) {
    u64 d; asm("fma.rn.f32x2 %0, %1, %2, %3;" : "=l"(d) : "l"(a), "l"(b), "l"(c)); return d;
}
static __device__ __forceinline__ u64 add2_(u64 a, u64 b) {
    u64 d; asm("add.rn.f32x2 %0, %1, %2;" : "=l"(d) : "l"(a), "l"(b)); return d;
}
static __device__ __forceinline__ u64 neg2_(u64 a) { return a ^ 0x8000000080000000ULL; }

static __device__ __forceinline__ u64 shfl_dn2(u64 v) {
    float a, b; upk2(v, a, b);
    a = __shfl_down_sync(FULL, a, 1);
    b = __shfl_down_sync(FULL, b, 1);
    return pk2(a, b);
}
static __device__ __forceinline__ u64 shfl_up2(u64 v) {
    float a, b; upk2(v, a, b);
    a = __shfl_up_sync(FULL, a, 1);
    b = __shfl_up_sync(FULL, b, 1);
    return pk2(a, b);
}

static __device__ __forceinline__ float soft_alpha(float a, float b) {
    return atanf(STEEP * (b - a)) * INV_PI + 0.5f;
}

// ---------------------------------------------------------------------------
// Kernel A: one warp per batch, x in registers (lane l owns x[4l..4l+3]).
// Halo ghosts make odd layers fully local: ghost neighbors' even-layer updates
// are recomputed locally (latency-parallel atanfs), so no shuffle sits on the
// serial critical path. Alphas emitted as one float4 per layer-pair.
// ---------------------------------------------------------------------------
__global__ __launch_bounds__(32) void alpha_kernel(const float* __restrict__ in,
                                                   float* __restrict__ out_x) {
    const int b = blockIdx.x;
    const int l = threadIdx.x;

    const float4 xi = ((const float4*)(in + b * N))[l];
    float x0 = xi.x, x1 = xi.y, x2 = xi.z, x3 = xi.w;

    float4* aout = g_alphas4 + (size_t)b * (LAYERS / 2) * 32;

    #pragma unroll 4
    for (int L = 0; L < LAYERS; L += 2) {
        // ghost refresh (previous-iteration values -> off the chain)
        float gr0 = __shfl_down_sync(FULL, x0, 1); // next lane x0
        float gr1 = __shfl_down_sync(FULL, x1, 1); // next lane x1
        float gl2 = __shfl_up_sync  (FULL, x2, 1); // prev lane x2
        float gl3 = __shfl_up_sync  (FULL, x3, 1); // prev lane x3

        // ---- even layer L ----
        float d0  = x0 - x1,  d1  = x2 - x3;
        float dgr = gr0 - gr1, dgl = gl2 - gl3;
        float al0 = soft_alpha(x0, x1);
        float al1 = soft_alpha(x2, x3);
        float agr = soft_alpha(gr0, gr1);
        float agl = soft_alpha(gl2, gl3);
        float n0 = fmaf(al0, d0, x1);
        float n1 = fmaf(-al0, d0, x0);
        float n2 = fmaf(al1, d1, x3);
        float n3 = fmaf(-al1, d1, x2);
        float gr0n = fmaf(agr, dgr, gr1);   // neighbor's new x0 (exact replica)
        float gl3n = fmaf(-agl, dgl, gl2);  // prev neighbor's new x3
        x0 = n0; x1 = n1; x2 = n2; x3 = n3;

        // ---- odd layer L+1 (fully local) ----
        float dm = x1 - x2;
        float am = soft_alpha(x1, x2);
        float dc = x3 - gr0n;
        float ac = soft_alpha(x3, gr0n);            // pair (4l+3, 4l+4)
        float dl = gl3n - x0;
        float apre = soft_alpha(gl3n, x0);          // pair (4l-1, 4l)
        float nx1 = fmaf(am, dm, x2);
        float nx2 = fmaf(-am, dm, x1);
        x3 = (l < 31) ? fmaf(ac, dc, gr0n) : x3;
        x0 = (l > 0)  ? fmaf(-apre, dl, gl3n) : x0;
        x1 = nx1; x2 = nx2;

        aout[(L >> 1) * 32 + l] = make_float4(al0, al1, am, ac);
    }

    ((float4*)(out_x + b * N))[l] = make_float4(x0, x1, x2, x3);
}

// ---------------------------------------------------------------------------
// Kernel B: each warp owns 2 rows of X, packed two-rows-per-register (f32x2).
// Lane l holds cols 4l..4l+3 for both rows in 4 u64 regs. 4096 warps,
// no barriers/branches in the layer loop.
// grid = BATCH*8 CTAs x 256 threads.
// ---------------------------------------------------------------------------
__global__ __launch_bounds__(256) void mix_kernel(float* __restrict__ out_X) {
    __shared__ float4 As[(LAYERS / 2) * 32];   // 32 KB

    const int b   = blockIdx.x >> 3;
    const int grp = blockIdx.x & 7;
    const int tid = threadIdx.x;

    {
        const float4* src = g_alphas4 + (size_t)b * (LAYERS / 2) * 32;
        #pragma unroll
        for (int i = 0; i < (LAYERS / 2) * 32 / 256; ++i)
            As[tid + i * 256] = src[tid + i * 256];
    }
    __syncthreads();

    const int warp = tid >> 5;
    const int lane = tid & 31;
    const int row0 = grp * 16 + warp * 2;

    // identity init, rows (row0, row0+1) packed
    u64 P[4];
    #pragma unroll
    for (int j = 0; j < 4; ++j) {
        int col = 4 * lane + j;
        P[j] = pk2(row0 == col ? 1.0f : 0.0f, (row0 + 1) == col ? 1.0f : 0.0f);
    }

    #pragma unroll 4
    for (int L2 = 0; L2 < LAYERS / 2; ++L2) {
        float4 a = As[L2 * 32 + lane];   // {al0, al1, am, ac}

        // ---- even layer ----
        u64 a0s = pk2(a.x, a.x);
        u64 a1s = pk2(a.y, a.y);
        {
            u64 d0 = add2_(P[0], neg2_(P[1]));
            u64 c0 = fma2_(a0s, d0, P[1]);
            u64 c1 = fma2_(a0s, neg2_(d0), P[0]);
            P[0] = c0; P[1] = c1;
            u64 d1 = add2_(P[2], neg2_(P[3]));
            u64 c2 = fma2_(a1s, d1, P[3]);
            u64 c3 = fma2_(a1s, neg2_(d1), P[2]);
            P[2] = c2; P[3] = c3;
        }

        // ---- odd layer ----
        float ap  = __shfl_up_sync(FULL, a.w, 1);
        float b1z = (lane == 31) ? 0.0f : (1.0f - a.w);
        float bpz = (lane == 0)  ? 0.0f : (1.0f - ap);
        u64 ams = pk2(a.z, a.z);
        u64 b1s = pk2(b1z, b1z);
        u64 bps = pk2(bpz, bpz);
        {
            u64 nb = shfl_dn2(P[0]);  // next lane's col 4l+4 (old)
            u64 pa = shfl_up2(P[3]);  // prev lane's col 4l-1 (old)
            u64 d  = add2_(P[1], neg2_(P[2]));
            u64 n1 = fma2_(ams, d, P[2]);
            u64 n2 = fma2_(ams, neg2_(d), P[1]);
            P[3] = fma2_(b1s, add2_(nb, neg2_(P[3])), P[3]);  // no-op lane31
            P[0] = fma2_(bps, add2_(pa, neg2_(P[0])), P[0]);  // no-op lane0
            P[1] = n1; P[2] = n2;
        }
    }

    float* outb = out_X + (size_t)b * N * N;
    float r0v[4], r1v[4];
    #pragma unroll
    for (int j = 0; j < 4; ++j) upk2(P[j], r0v[j], r1v[j]);
    ((float4*)(outb + row0 * N))[lane]       = make_float4(r0v[0], r0v[1], r0v[2], r0v[3]);
    ((float4*)(outb + (row0 + 1) * N))[lane] = make_float4(r1v[0], r1v[1], r1v[2], r1v[3]);
}

extern "C" void kernel_launch(void* const* d_in, const int* in_sizes, int n_in,
                              void* d_out, int out_size) {
    (void)in_sizes; (void)n_in; (void)out_size;
    const float* vec = (const float*)d_in[0];
    float* out = (float*)d_out;

    // output layout: [x (64*128)] then [X (64*128*128)]
    alpha_kernel<<<BATCH, 32>>>(vec, out);
    mix_kernel<<<BATCH * 8, 256>>>(out + BATCH * N);
}

// round 12
// speedup vs baseline: 2.8201x; 1.0579x over previous
#include <cuda_runtime.h>

#define BATCH   64
#define N       128
#define LAYERS  128
#define PAIRS   64
#define STEEP   10.0f
#define INV_PI  0.318309886183790671538f
#define FULL    0xffffffffu

// alphas[batch][layer_pair][pair] as float4 {al0, al1, am, ac}  (2 MB)
__device__ float4 g_alphas4[BATCH * (LAYERS / 2) * 32];

static __device__ __forceinline__ float soft_alpha(float a, float b) {
    return atanf(STEEP * (b - a)) * INV_PI + 0.5f;
}

// ---------------------------------------------------------------------------
// Kernel A (R9-proven form): one warp per batch, x in registers
// (lane l owns x[4l..4l+3]). Serial 128-layer chain, shuffles on odd layers,
// branchless edge handling. One float4 alpha store per layer-pair.
// ---------------------------------------------------------------------------
__global__ __launch_bounds__(32) void alpha_kernel(const float* __restrict__ in,
                                                   float* __restrict__ out_x) {
    const int b = blockIdx.x;
    const int l = threadIdx.x;

    const float4 xi = ((const float4*)(in + b * N))[l];
    float x0 = xi.x, x1 = xi.y, x2 = xi.z, x3 = xi.w;

    float4* aout = g_alphas4 + (size_t)b * (LAYERS / 2) * 32;

    #pragma unroll 2
    for (int L = 0; L < LAYERS; L += 2) {
        // ---- even layer L: pairs (4l,4l+1), (4l+2,4l+3) intra-lane ----
        float d0 = x0 - x1;
        float d1 = x2 - x3;
        float al0 = soft_alpha(x0, x1);
        float al1 = soft_alpha(x2, x3);
        float n0 = fmaf(al0, d0, x1);
        float n1 = fmaf(-al0, d0, x0);
        float n2 = fmaf(al1, d1, x3);
        float n3 = fmaf(-al1, d1, x2);
        x0 = n0; x1 = n1; x2 = n2; x3 = n3;

        // ---- odd layer L+1: (4l+1,4l+2) intra; (4l+3,4l+4) cross ----
        float bn = __shfl_down_sync(FULL, x0, 1); // next lane's x0 (old)
        float pa = __shfl_up_sync  (FULL, x3, 1); // prev lane's x3 (old)
        float dm = x1 - x2;
        float am = soft_alpha(x1, x2);
        float dc = x3 - bn;
        float ac = soft_alpha(x3, bn);
        float alp = __shfl_up_sync(FULL, ac, 1);
        float b1z = (l == 31) ? 0.0f : (1.0f - ac);
        float bpz = (l == 0)  ? 0.0f : (1.0f - alp);
        float nx1 = fmaf(am, dm, x2);
        float nx2 = fmaf(-am, dm, x1);
        x3 = fmaf(b1z, bn - x3, x3);   // no-op on lane 31
        x0 = fmaf(bpz, pa - x0, x0);   // no-op on lane 0
        x1 = nx1; x2 = nx2;

        aout[(L >> 1) * 32 + l] = make_float4(al0, al1, am, ac);
    }

    ((float4*)(out_x + b * N))[l] = make_float4(x0, x1, x2, x3);
}

// ---------------------------------------------------------------------------
// Kernel B: each warp owns ONE row of X, register-resident (lane l holds
// cols 4l..4l+3). 8192 warps total -> grid-limited occupancy lifted.
// No barriers/branches inside the layer loop.
// grid = BATCH*16 CTAs x 256 threads (8 warps -> 8 rows per CTA).
// ---------------------------------------------------------------------------
__global__ __launch_bounds__(256) void mix_kernel(float* __restrict__ out_X) {
    __shared__ float4 As[(LAYERS / 2) * 32];   // 32 KB

    const int b   = blockIdx.x >> 4;
    const int grp = blockIdx.x & 15;
    const int tid = threadIdx.x;

    {
        const float4* src = g_alphas4 + (size_t)b * (LAYERS / 2) * 32;
        #pragma unroll
        for (int i = 0; i < (LAYERS / 2) * 32 / 256; ++i)
            As[tid + i * 256] = src[tid + i * 256];
    }
    __syncthreads();

    const int warp = tid >> 5;
    const int lane = tid & 31;
    const int row  = grp * 8 + warp;

    // identity row
    float c0 = (row == 4 * lane + 0) ? 1.0f : 0.0f;
    float c1 = (row == 4 * lane + 1) ? 1.0f : 0.0f;
    float c2 = (row == 4 * lane + 2) ? 1.0f : 0.0f;
    float c3 = (row == 4 * lane + 3) ? 1.0f : 0.0f;

    #pragma unroll 4
    for (int L2 = 0; L2 < LAYERS / 2; ++L2) {
        float4 a = As[L2 * 32 + lane];   // {al0, al1, am, ac}

        // ---- even layer ----
        float d0 = c0 - c1;
        float t0 = fmaf(a.x, d0, c1);
        float t1 = fmaf(-a.x, d0, c0);
        float d1 = c2 - c3;
        float t2 = fmaf(a.y, d1, c3);
        float t3 = fmaf(-a.y, d1, c2);
        c0 = t0; c1 = t1; c2 = t2; c3 = t3;

        // ---- odd layer ----
        float ap  = __shfl_up_sync(FULL, a.w, 1);
        float b1z = (lane == 31) ? 0.0f : (1.0f - a.w);
        float bpz = (lane == 0)  ? 0.0f : (1.0f - ap);
        float nb = __shfl_down_sync(FULL, c0, 1); // next lane's col 4l+4 (old)
        float pa = __shfl_up_sync  (FULL, c3, 1); // prev lane's col 4l-1 (old)
        float dm = c1 - c2;
        float n1 = fmaf(a.z, dm, c2);
        float n2 = fmaf(-a.z, dm, c1);
        c3 = fmaf(b1z, nb - c3, c3);   // no-op on lane 31
        c0 = fmaf(bpz, pa - c0, c0);   // no-op on lane 0
        c1 = n1; c2 = n2;
    }

    float* outb = out_X + (size_t)b * N * N;
    ((float4*)(outb + row * N))[lane] = make_float4(c0, c1, c2, c3);
}

extern "C" void kernel_launch(void* const* d_in, const int* in_sizes, int n_in,
                              void* d_out, int out_size) {
    (void)in_sizes; (void)n_in; (void)out_size;
    const float* vec = (const float*)d_in[0];
    float* out = (float*)d_out;

    // output layout: [x (64*128)] then [X (64*128*128)]
    alpha_kernel<<<BATCH, 32>>>(vec, out);
    mix_kernel<<<BATCH * 16, 256>>>(out + BATCH * N);
}

// round 13
// speedup vs baseline: 3.2724x; 1.1604x over previous
#include <cuda_runtime.h>

#define BATCH   64
#define N       128
#define LAYERS  128
#define PAIRS   64
#define STEEP   10.0f
#define INV_PI  0.318309886183790671538f
#define FULL    0xffffffffu

// coefficient arrays written by producer, read by consumer:
// g_alphas4[b][L2][lane] = {al0, al1, am, b1z}; g_bpz[b][L2][lane] = bpz
__device__ float4 g_alphas4[BATCH * (LAYERS / 2) * 32];
__device__ float  g_bpz   [BATCH * (LAYERS / 2) * 32];

// fast soft-compare alpha: atan(STEEP*(b-a))/pi + 0.5, abs err ~1e-5
static __device__ __forceinline__ float fast_alpha(float a, float b) {
    float y  = STEEP * (b - a);
    float ay = fabsf(y);
    bool big = ay > 1.0f;
    float t  = big ? __fdividef(1.0f, y) : y;
    float z  = t * t;
    float p  =          -0.0117212f;
    p = fmaf(p, z,  0.05265332f);
    p = fmaf(p, z, -0.11643287f);
    p = fmaf(p, z,  0.19354346f);
    p = fmaf(p, z, -0.33262347f);
    p = fmaf(p, z,  0.99997726f);
    p = p * t;                                   // ~atan(t)
    float r = big ? (copysignf(1.57079632679f, y) - p) : p;
    return fmaf(r, INV_PI, 0.5f);
}

// ---------------------------------------------------------------------------
// Kernel A: one warp per batch, x in registers (lane l owns x[4l..4l+3]).
// Serial 128-layer chain with fast_alpha on the critical path. Also emits the
// consumer-ready coefficients {al0, al1, am, b1z} + bpz (edge-zeroed).
// ---------------------------------------------------------------------------
__global__ __launch_bounds__(32) void alpha_kernel(const float* __restrict__ in,
                                                   float* __restrict__ out_x) {
    const int b = blockIdx.x;
    const int l = threadIdx.x;

    const float4 xi = ((const float4*)(in + b * N))[l];
    float x0 = xi.x, x1 = xi.y, x2 = xi.z, x3 = xi.w;

    float4* aout = g_alphas4 + (size_t)b * (LAYERS / 2) * 32;
    float*  bout = g_bpz     + (size_t)b * (LAYERS / 2) * 32;

    #pragma unroll 2
    for (int L = 0; L < LAYERS; L += 2) {
        // ---- even layer: pairs (4l,4l+1), (4l+2,4l+3) intra-lane ----
        float d0 = x0 - x1;
        float d1 = x2 - x3;
        float al0 = fast_alpha(x0, x1);
        float al1 = fast_alpha(x2, x3);
        float n0 = fmaf(al0, d0, x1);
        float n1 = fmaf(-al0, d0, x0);
        float n2 = fmaf(al1, d1, x3);
        float n3 = fmaf(-al1, d1, x2);
        x0 = n0; x1 = n1; x2 = n2; x3 = n3;

        // ---- odd layer: (4l+1,4l+2) intra; (4l+3,4l+4) cross ----
        float bn = __shfl_down_sync(FULL, x0, 1); // next lane's x0 (old)
        float pa = __shfl_up_sync  (FULL, x3, 1); // prev lane's x3 (old)
        float dm = x1 - x2;
        float am = fast_alpha(x1, x2);
        float ac = fast_alpha(x3, bn);
        float alp = __shfl_up_sync(FULL, ac, 1);
        float b1z = (l == 31) ? 0.0f : (1.0f - ac);
        float bpz = (l == 0)  ? 0.0f : (1.0f - alp);
        float nx1 = fmaf(am, dm, x2);
        float nx2 = fmaf(-am, dm, x1);
        x3 = fmaf(b1z, bn - x3, x3);   // no-op on lane 31
        x0 = fmaf(bpz, pa - x0, x0);   // no-op on lane 0
        x1 = nx1; x2 = nx2;

        aout[(L >> 1) * 32 + l] = make_float4(al0, al1, am, b1z);
        bout[(L >> 1) * 32 + l] = bpz;
    }

    ((float4*)(out_x + b * N))[l] = make_float4(x0, x1, x2, x3);
}

// ---------------------------------------------------------------------------
// Kernel B: each warp owns 2 rows of X, register-resident (lane l holds
// cols 4l..4l+3 of both rows). Coefficients fully precomputed by producer:
// 1 LDS.128 + 1 LDS.32 per warp per 2 layers, zero coefficient ALU.
// grid = BATCH*8 CTAs x 256 threads (R9's proven occupancy point).
// ---------------------------------------------------------------------------
__global__ __launch_bounds__(256) void mix_kernel(float* __restrict__ out_X) {
    __shared__ float4 As[(LAYERS / 2) * 32];   // 32 KB
    __shared__ float  Bs[(LAYERS / 2) * 32];   //  8 KB

    const int b   = blockIdx.x >> 3;
    const int grp = blockIdx.x & 7;
    const int tid = threadIdx.x;

    {
        const float4* src = g_alphas4 + (size_t)b * (LAYERS / 2) * 32;
        #pragma unroll
        for (int i = 0; i < (LAYERS / 2) * 32 / 256; ++i)
            As[tid + i * 256] = src[tid + i * 256];
        const float4* srcb = (const float4*)(g_bpz + (size_t)b * (LAYERS / 2) * 32);
        float4* dstb = (float4*)Bs;
        #pragma unroll
        for (int i = 0; i < (LAYERS / 2) * 32 / 4 / 256; ++i)
            dstb[tid + i * 256] = srcb[tid + i * 256];
    }
    __syncthreads();

    const int warp = tid >> 5;
    const int lane = tid & 31;
    const int row0 = grp * 16 + warp * 2;

    // identity rows row0, row0+1 (suffix a = row0, b = row0+1)
    float c0a = (row0 == 4 * lane + 0) ? 1.0f : 0.0f;
    float c1a = (row0 == 4 * lane + 1) ? 1.0f : 0.0f;
    float c2a = (row0 == 4 * lane + 2) ? 1.0f : 0.0f;
    float c3a = (row0 == 4 * lane + 3) ? 1.0f : 0.0f;
    float c0b = (row0 + 1 == 4 * lane + 0) ? 1.0f : 0.0f;
    float c1b = (row0 + 1 == 4 * lane + 1) ? 1.0f : 0.0f;
    float c2b = (row0 + 1 == 4 * lane + 2) ? 1.0f : 0.0f;
    float c3b = (row0 + 1 == 4 * lane + 3) ? 1.0f : 0.0f;

    #pragma unroll 4
    for (int L2 = 0; L2 < LAYERS / 2; ++L2) {
        float4 a  = As[L2 * 32 + lane];   // {al0, al1, am, b1z}
        float bpz = Bs[L2 * 32 + lane];

        // ---- even layer ----
        {
            float d0 = c0a - c1a;
            float t0 = fmaf(a.x, d0, c1a);
            float t1 = fmaf(-a.x, d0, c0a);
            float d1 = c2a - c3a;
            float t2 = fmaf(a.y, d1, c3a);
            float t3 = fmaf(-a.y, d1, c2a);
            c0a = t0; c1a = t1; c2a = t2; c3a = t3;
        }
        {
            float d0 = c0b - c1b;
            float t0 = fmaf(a.x, d0, c1b);
            float t1 = fmaf(-a.x, d0, c0b);
            float d1 = c2b - c3b;
            float t2 = fmaf(a.y, d1, c3b);
            float t3 = fmaf(-a.y, d1, c2b);
            c0b = t0; c1b = t1; c2b = t2; c3b = t3;
        }

        // ---- odd layer ----
        {
            float nb = __shfl_down_sync(FULL, c0a, 1);
            float pa = __shfl_up_sync  (FULL, c3a, 1);
            float dm = c1a - c2a;
            float n1 = fmaf(a.z, dm, c2a);
            float n2 = fmaf(-a.z, dm, c1a);
            c3a = fmaf(a.w, nb - c3a, c3a);   // no-op lane 31 (b1z = 0)
            c0a = fmaf(bpz, pa - c0a, c0a);   // no-op lane 0  (bpz = 0)
            c1a = n1; c2a = n2;
        }
        {
            float nb = __shfl_down_sync(FULL, c0b, 1);
            float pa = __shfl_up_sync  (FULL, c3b, 1);
            float dm = c1b - c2b;
            float n1 = fmaf(a.z, dm, c2b);
            float n2 = fmaf(-a.z, dm, c1b);
            c3b = fmaf(a.w, nb - c3b, c3b);
            c0b = fmaf(bpz, pa - c0b, c0b);
            c1b = n1; c2b = n2;
        }
    }

    float* outb = out_X + (size_t)b * N * N;
    ((float4*)(outb + row0 * N))[lane]       = make_float4(c0a, c1a, c2a, c3a);
    ((float4*)(outb + (row0 + 1) * N))[lane] = make_float4(c0b, c1b, c2b, c3b);
}

extern "C" void kernel_launch(void* const* d_in, const int* in_sizes, int n_in,
                              void* d_out, int out_size) {
    (void)in_sizes; (void)n_in; (void)out_size;
    const float* vec = (const float*)d_in[0];
    float* out = (float*)d_out;

    // output layout: [x (64*128)] then [X (64*128*128)]
    alpha_kernel<<<BATCH, 32>>>(vec, out);
    mix_kernel<<<BATCH * 8, 256>>>(out + BATCH * N);
}